// round 10
// baseline (speedup 1.0000x reference)
#include <cuda_runtime.h>

#define FULL 0xffffffffu
typedef unsigned int u32;

constexpr int L = 16;
constexpr float LOG2E = 1.4426950408889634f;
constexpr float LN2   = 0.6931471805599453f;

__device__ __forceinline__ float ex2f(float v) {
    float r; asm("ex2.approx.f32 %0,%1;" : "=f"(r) : "f"(v)); return r;
}
__device__ __forceinline__ u32 pkbf(float hi, float lo) {
    u32 r; asm("cvt.rn.bf16x2.f32 %0,%1,%2;" : "=r"(r) : "f"(hi), "f"(lo)); return r;
}
__device__ __forceinline__ u32 mulbf2(u32 a, u32 b) {
    u32 r; asm("mul.rn.bf16x2 %0,%1,%2;" : "=r"(r) : "r"(a), "r"(b)); return r;
}
__device__ __forceinline__ float bflo(u32 v) { return __uint_as_float(v << 16); }
__device__ __forceinline__ float bfhi(u32 v) { return __uint_as_float(v & 0xffff0000u); }

__device__ __forceinline__ void mma16816(
    float& d0, float& d1, float& d2, float& d3,
    u32 a0, u32 a1, u32 a2, u32 a3, u32 b0, u32 b1)
{
    asm volatile(
        "mma.sync.aligned.m16n8k16.row.col.f32.bf16.bf16.f32 "
        "{%0,%1,%2,%3}, {%4,%5,%6,%7}, {%8,%9}, {%10,%11,%12,%13};"
        : "=f"(d0), "=f"(d1), "=f"(d2), "=f"(d3)
        : "r"(a0), "r"(a1), "r"(a2), "r"(a3), "r"(b0), "r"(b1),
          "f"(0.f), "f"(0.f), "f"(0.f), "f"(0.f));
}

// state permutation on the MMA k/n axes: sigma(idx)
// idx<8 : even -> 2*idx,    odd -> 2*idx-1
// idx>=8: even -> 2*idx-14, odd -> 2*idx-15
__host__ __device__ __forceinline__ int sigma(int i) {
    return (i < 8) ? ((i & 1) ? 2 * i - 1 : 2 * i)
                   : ((i & 1) ? 2 * i - 15 : 2 * i - 14);
}

// Grid = 64 blocks x 64 batches. Block = 512 threads = 16 warps:
//  w0-3 : fwd recursion, batch groups 0-3 (16 batches each)
//  w4-7 : bwd recursion, groups 0-3
//  w8-15: emit + transition scores (8 batches each)
// SMSP k hosts fwd-grpk + bwd-grpk (2 independent chains) + 2 emit warps.
// State s = A-fragment (bf16) of m16n8k16 with sigma-permuted state axes,
// so thread tig owns contiguous states 4*tig..4*tig+3 (float4 x loads, no
// cross-lane repack D->A).
__global__ __launch_bounds__(512, 1) void crf_kernel(
    const float* __restrict__ x, const float* __restrict__ trans,
    const int* __restrict__ label, const int* __restrict__ length,
    float* __restrict__ out, int B, int T)
{
    __shared__ float sE[L * L];
    __shared__ float sT[L * L];
    __shared__ u32   sFA[4][32][4];
    __shared__ int   sMf[4][16];
    __shared__ float sScore[64];

    int tid  = threadIdx.x;
    int lane = tid & 31;
    int w    = tid >> 5;
    int g    = lane >> 2;
    int tig  = lane & 3;

    if (tid < L * L) {
        float tv = trans[tid];
        sT[tid] = tv;
        sE[tid] = tv * LOG2E;
    }
    __syncthreads();

    int blockBase = blockIdx.x * 64;

    if (w < 8) {
        bool isBwd = w >= 4;
        int grp = w & 3;
        int bBase = blockBase + grp * 16;
        int b_lo = bBase + g, b_hi = bBase + g + 8;
        int lenL = length[b_lo], lenH = length[b_hi];
        int mL = (lenL - 1) >> 1, mH = (lenH - 1) >> 1;
        int cntL = isBwd ? max(lenL - 2 - mL, 0) : mL;
        int cntH = isBwd ? max(lenH - 2 - mH, 0) : mH;
        int baseL = isBwd ? (lenL - 2) : 1;
        int baseH = isBwd ? (lenH - 2) : 1;
        int dir   = isBwd ? -1 : 1;
        int clL = max(cntL - 1, 0), clH = max(cntH - 1, 0);

        int kMax = max(cntL, cntH);
#pragma unroll
        for (int o = 1; o <= 16; o <<= 1)
            kMax = max(kMax, __shfl_xor_sync(FULL, kMax, o));
        int kMaxPad = (kMax + 3) & ~3;

        // B fragments with sigma on both axes:
        // fwd: B[kap][n] = expE[sigma(kap)][sigma(n)];  bwd: transpose roles.
        u32 b00, b01, b10, b11;
        {
            int r0 = 4 * tig;            // sigma of kap-pairs for this thread
            int cA = sigma(g);           // MMA1 n-column
            int cB = sigma(g + 8);       // MMA2 n-column
            float e00, e01, e02, e03, e10, e11, e12, e13;
            if (!isBwd) {
                e00 = sE[r0 * L + cA];       e01 = sE[(r0 + 1) * L + cA];
                e02 = sE[(r0 + 2) * L + cA]; e03 = sE[(r0 + 3) * L + cA];
                e10 = sE[r0 * L + cB];       e11 = sE[(r0 + 1) * L + cB];
                e12 = sE[(r0 + 2) * L + cB]; e13 = sE[(r0 + 3) * L + cB];
            } else {
                e00 = sE[cA * L + r0];       e01 = sE[cA * L + r0 + 1];
                e02 = sE[cA * L + r0 + 2];   e03 = sE[cA * L + r0 + 3];
                e10 = sE[cB * L + r0];       e11 = sE[cB * L + r0 + 1];
                e12 = sE[cB * L + r0 + 2];   e13 = sE[cB * L + r0 + 3];
            }
            b00 = pkbf(ex2f(e01), ex2f(e00));
            b01 = pkbf(ex2f(e03), ex2f(e02));
            b10 = pkbf(ex2f(e11), ex2f(e10));
            b11 = pkbf(ex2f(e13), ex2f(e12));
        }

        // x pointers: thread tig owns states 4*tig..4*tig+3 (one float4)
        const float* pL = x + (size_t)b_lo * T * L + tig * 4;
        const float* pH = x + (size_t)b_hi * T * L + tig * 4;

        // init: s = exp(x at row 0 (fwd) / len-1 (bwd))
        int irL = isBwd ? (lenL - 1) : 0;
        int irH = isBwd ? (lenH - 1) : 0;
        float4 iL = *(const float4*)(pL + (size_t)irL * L);
        float4 iH = *(const float4*)(pH + (size_t)irH * L);
        u32 A0 = pkbf(ex2f(iL.y * LOG2E), ex2f(iL.x * LOG2E));  // row g,   states 4t..4t+1
        u32 A1 = pkbf(ex2f(iH.y * LOG2E), ex2f(iH.x * LOG2E));  // row g+8
        u32 A2 = pkbf(ex2f(iL.w * LOG2E), ex2f(iL.z * LOG2E));  // row g,   states 4t+2..4t+3
        u32 A3 = pkbf(ex2f(iH.w * LOG2E), ex2f(iH.z * LOG2E));  // row g+8
        int MsL = 0, MsH = 0;

        // 4-deep prefetch ring of x rows (clamped)
        float4 rL[4], rH[4];
#pragma unroll
        for (int d = 0; d < 4; ++d) {
            int rowL = max(baseL + dir * min(d, clL), 0);
            int rowH = max(baseH + dir * min(d, clH), 0);
            rL[d] = *(const float4*)(pL + (size_t)rowL * L);
            rH[d] = *(const float4*)(pH + (size_t)rowH * L);
        }

        for (int k0 = 0; k0 < kMaxPad; k0 += 4) {
#pragma unroll
            for (int kk = 0; kk < 4; ++kk) {
                int k = k0 + kk;

                float4 xL = rL[kk], xH = rH[kk];

                float eL0 = ex2f(xL.x * LOG2E), eL1 = ex2f(xL.y * LOG2E);
                float eL2 = ex2f(xL.z * LOG2E), eL3 = ex2f(xL.w * LOG2E);
                float eH0 = ex2f(xH.x * LOG2E), eH1 = ex2f(xH.y * LOG2E);
                float eH2 = ex2f(xH.z * LOG2E), eH3 = ex2f(xH.w * LOG2E);

                float d0, d1, d2, d3, f0, f1, f2, f3;
                mma16816(d0, d1, d2, d3, A0, A1, A2, A3, b00, b01);
                mma16816(f0, f1, f2, f3, A0, A1, A2, A3, b10, b11);

                // refill ring slot with row k+4
                {
                    int rowL = max(baseL + dir * min(k + 4, clL), 0);
                    int rowH = max(baseH + dir * min(k + 4, clH), 0);
                    rL[kk] = *(const float4*)(pL + (size_t)rowL * L);
                    rH[kk] = *(const float4*)(pH + (size_t)rowH * L);
                }

                u32 n0 = mulbf2(pkbf(d1, d0), pkbf(eL1, eL0));
                u32 n1 = mulbf2(pkbf(d3, d2), pkbf(eH1, eH0));
                u32 n2 = mulbf2(pkbf(f1, f0), pkbf(eL3, eL2));
                u32 n3 = mulbf2(pkbf(f3, f2), pkbf(eH3, eH2));

                bool aL = k < cntL, aH = k < cntH;
                A0 = aL ? n0 : A0;  A2 = aL ? n2 : A2;
                A1 = aH ? n1 : A1;  A3 = aH ? n3 : A3;

                if ((k & 7) == 7) {   // exponent-only rescale per batch row
                    u32 s0 = __shfl_sync(FULL, A0, lane & ~3);   // state 0 in lo half
                    u32 s1 = __shfl_sync(FULL, A1, lane & ~3);
                    int eeL = (int)((s0 >> 7) & 0xff) - 127;
                    int eeH = (int)((s1 >> 7) & 0xff) - 127;
                    u32 hL = (u32)(127 - eeL) << 7;
                    u32 hH = (u32)(127 - eeH) << 7;
                    u32 scL = aL ? (hL | (hL << 16)) : 0x3f803f80u;
                    u32 scH = aH ? (hH | (hH << 16)) : 0x3f803f80u;
                    MsL += aL ? eeL : 0;
                    MsH += aH ? eeH : 0;
                    A0 = mulbf2(A0, scL); A2 = mulbf2(A2, scL);
                    A1 = mulbf2(A1, scH); A3 = mulbf2(A3, scH);
                }
            }
        }

        if (!isBwd) {
            sFA[grp][lane][0] = A0; sFA[grp][lane][1] = A1;
            sFA[grp][lane][2] = A2; sFA[grp][lane][3] = A3;
            if (tig == 0) { sMf[grp][g] = MsL; sMf[grp][g + 8] = MsH; }
            __syncthreads();
        } else {
            // beta_m = E * q~ : one more (plain) double-MMA
            float d0, d1, d2, d3, f0, f1, f2, f3;
            mma16816(d0, d1, d2, d3, A0, A1, A2, A3, b00, b01);
            mma16816(f0, f1, f2, f3, A0, A1, A2, A3, b10, b11);
            if (lenL == 1) { d0 = d1 = 1.f; f0 = f1 = 1.f; }
            if (lenH == 1) { d2 = d3 = 1.f; f2 = f3 = 1.f; }

            __syncthreads();

            u32 a0 = sFA[grp][lane][0], a1 = sFA[grp][lane][1];
            u32 a2 = sFA[grp][lane][2], a3 = sFA[grp][lane][3];
            float pLo = d0 * bflo(a0) + d1 * bfhi(a0) + f0 * bflo(a2) + f1 * bfhi(a2);
            float pHi = d2 * bflo(a1) + d3 * bfhi(a1) + f2 * bflo(a3) + f3 * bfhi(a3);
            pLo += __shfl_xor_sync(FULL, pLo, 1);
            pLo += __shfl_xor_sync(FULL, pLo, 2);
            pHi += __shfl_xor_sync(FULL, pHi, 1);
            pHi += __shfl_xor_sync(FULL, pHi, 2);
            float zL = __logf(pLo) + (float)(MsL + sMf[grp][g]) * LN2;
            float zH = __logf(pHi) + (float)(MsH + sMf[grp][g + 8]) * LN2;
            if (tig == 0) {
                out[b_lo] = zL - sScore[grp * 16 + g];
                out[b_hi] = zH - sScore[grp * 16 + g + 8];
            }
        }
    } else {
        // ---------------- emit / transition warps ----------------
        int we = w - 8;
#pragma unroll 1
        for (int k2 = 0; k2 < 8; ++k2) {
            int sl = we * 8 + k2;
            int bb = blockBase + sl;
            const int*   lb = label + (size_t)bb * T;
            const float* xb = x + (size_t)bb * T * L;
            int ll = length[bb];

            float acc = 0.f;
            for (int t = lane; t < ll; t += 32) {
                int lab = lb[t];
                acc += __ldg(xb + t * L + lab);
                if (t >= 1) acc += sT[lb[t - 1] * L + lab];
            }
            acc += __shfl_xor_sync(FULL, acc, 16);
            acc += __shfl_xor_sync(FULL, acc, 8);
            acc += __shfl_xor_sync(FULL, acc, 4);
            acc += __shfl_xor_sync(FULL, acc, 2);
            acc += __shfl_xor_sync(FULL, acc, 1);
            if (lane == 0) sScore[sl] = acc;
        }
        __syncthreads();
    }
}

extern "C" void kernel_launch(void* const* d_in, const int* in_sizes, int n_in,
                              void* d_out, int out_size) {
    const float* x      = (const float*)d_in[0];
    const float* trans  = (const float*)d_in[1];
    const int*   label  = (const int*)d_in[2];
    const int*   length = (const int*)d_in[3];
    float*       out    = (float*)d_out;

    int B = in_sizes[3];                 // 4096
    int T = in_sizes[2] / B;             // 512

    int grid = (B + 63) / 64;            // 64 batches per block, 64 blocks
    crf_kernel<<<grid, 512>>>(x, trans, label, length, out, B, T);
}

// round 11
// speedup vs baseline: 1.3649x; 1.3649x over previous
#include <cuda_runtime.h>

#define FULL 0xffffffffu
typedef unsigned int u32;

constexpr int L = 16;
constexpr float LOG2E = 1.4426950408889634f;
constexpr float LN2   = 0.6931471805599453f;

__device__ __forceinline__ float ex2f(float v) {
    float r; asm("ex2.approx.f32 %0,%1;" : "=f"(r) : "f"(v)); return r;
}
__device__ __forceinline__ u32 pkbf(float hi, float lo) {
    u32 r; asm("cvt.rn.bf16x2.f32 %0,%1,%2;" : "=r"(r) : "f"(hi), "f"(lo)); return r;
}
__device__ __forceinline__ u32 mulbf2(u32 a, u32 b) {
    u32 r; asm("mul.rn.bf16x2 %0,%1,%2;" : "=r"(r) : "r"(a), "r"(b)); return r;
}
__device__ __forceinline__ float bflo(u32 v) { return __uint_as_float(v << 16); }
__device__ __forceinline__ float bfhi(u32 v) { return __uint_as_float(v & 0xffff0000u); }

__device__ __forceinline__ void mma16816(
    float& d0, float& d1, float& d2, float& d3,
    u32 a0, u32 a1, u32 a2, u32 a3, u32 b0, u32 b1)
{
    asm volatile(
        "mma.sync.aligned.m16n8k16.row.col.f32.bf16.bf16.f32 "
        "{%0,%1,%2,%3}, {%4,%5,%6,%7}, {%8,%9}, {%10,%11,%12,%13};"
        : "=f"(d0), "=f"(d1), "=f"(d2), "=f"(d3)
        : "r"(a0), "r"(a1), "r"(a2), "r"(a3), "r"(b0), "r"(b1),
          "f"(0.f), "f"(0.f), "f"(0.f), "f"(0.f));
}

// state permutation on the MMA k/n axes
__host__ __device__ __forceinline__ int sigma(int i) {
    return (i < 8) ? ((i & 1) ? 2 * i - 1 : 2 * i)
                   : ((i & 1) ? 2 * i - 15 : 2 * i - 14);
}

// Grid = 128 blocks x 32 batches. Block = 256 threads = 8 warps:
//  w0-1: fwd recursion (batch groups 0-1, 16 batches each)
//  w2-3: bwd recursion (groups 0-1)
//  w4-7: emit + transition scores (8 batches each)
// -> exactly ONE recursion warp per SMSP across the full chip.
// State s = A-fragment (bf16) of m16n8k16 with sigma-permuted state axes:
// thread tig owns contiguous states 4*tig..4*tig+3 (float4 x loads, no
// cross-lane repack D->A).
__global__ __launch_bounds__(256, 1) void crf_kernel(
    const float* __restrict__ x, const float* __restrict__ trans,
    const int* __restrict__ label, const int* __restrict__ length,
    float* __restrict__ out, int B, int T)
{
    __shared__ float sE[L * L];
    __shared__ float sT[L * L];
    __shared__ u32   sFA[2][32][4];
    __shared__ int   sMf[2][16];
    __shared__ float sScore[32];

    int tid  = threadIdx.x;
    int lane = tid & 31;
    int w    = tid >> 5;
    int g    = lane >> 2;
    int tig  = lane & 3;

    if (tid < L * L) {
        float tv = trans[tid];
        sT[tid] = tv;
        sE[tid] = tv * LOG2E;
    }
    __syncthreads();

    int blockBase = blockIdx.x * 32;

    if (w < 4) {
        bool isBwd = w >= 2;
        int grp = w & 1;
        int bBase = blockBase + grp * 16;
        int b_lo = bBase + g, b_hi = bBase + g + 8;
        int lenL = length[b_lo], lenH = length[b_hi];
        int mL = (lenL - 1) >> 1, mH = (lenH - 1) >> 1;
        int cntL = isBwd ? max(lenL - 2 - mL, 0) : mL;
        int cntH = isBwd ? max(lenH - 2 - mH, 0) : mH;
        int baseL = isBwd ? (lenL - 2) : 1;
        int baseH = isBwd ? (lenH - 2) : 1;
        int dir   = isBwd ? -1 : 1;
        int clL = max(cntL - 1, 0), clH = max(cntH - 1, 0);

        int kMax = max(cntL, cntH);
#pragma unroll
        for (int o = 1; o <= 16; o <<= 1)
            kMax = max(kMax, __shfl_xor_sync(FULL, kMax, o));
        int kMaxPad = (kMax + 3) & ~3;

        // B fragments with sigma on both axes:
        // fwd: B[kap][n] = expE[sigma(kap)][sigma(n)];  bwd: transpose roles.
        u32 b00, b01, b10, b11;
        {
            int r0 = 4 * tig;
            int cA = sigma(g);
            int cB = sigma(g + 8);
            float e00, e01, e02, e03, e10, e11, e12, e13;
            if (!isBwd) {
                e00 = sE[r0 * L + cA];       e01 = sE[(r0 + 1) * L + cA];
                e02 = sE[(r0 + 2) * L + cA]; e03 = sE[(r0 + 3) * L + cA];
                e10 = sE[r0 * L + cB];       e11 = sE[(r0 + 1) * L + cB];
                e12 = sE[(r0 + 2) * L + cB]; e13 = sE[(r0 + 3) * L + cB];
            } else {
                e00 = sE[cA * L + r0];       e01 = sE[cA * L + r0 + 1];
                e02 = sE[cA * L + r0 + 2];   e03 = sE[cA * L + r0 + 3];
                e10 = sE[cB * L + r0];       e11 = sE[cB * L + r0 + 1];
                e12 = sE[cB * L + r0 + 2];   e13 = sE[cB * L + r0 + 3];
            }
            b00 = pkbf(ex2f(e01), ex2f(e00));
            b01 = pkbf(ex2f(e03), ex2f(e02));
            b10 = pkbf(ex2f(e11), ex2f(e10));
            b11 = pkbf(ex2f(e13), ex2f(e12));
        }

        // thread tig owns states 4*tig..4*tig+3 (one float4 per row)
        const float* pL = x + (size_t)b_lo * T * L + tig * 4;
        const float* pH = x + (size_t)b_hi * T * L + tig * 4;

        // init: s = exp(x at row 0 (fwd) / len-1 (bwd))
        int irL = isBwd ? (lenL - 1) : 0;
        int irH = isBwd ? (lenH - 1) : 0;
        float4 iL = *(const float4*)(pL + (size_t)irL * L);
        float4 iH = *(const float4*)(pH + (size_t)irH * L);
        u32 A0 = pkbf(ex2f(iL.y * LOG2E), ex2f(iL.x * LOG2E));
        u32 A1 = pkbf(ex2f(iH.y * LOG2E), ex2f(iH.x * LOG2E));
        u32 A2 = pkbf(ex2f(iL.w * LOG2E), ex2f(iL.z * LOG2E));
        u32 A3 = pkbf(ex2f(iH.w * LOG2E), ex2f(iH.z * LOG2E));
        int MsL = 0, MsH = 0;

        // 4-deep prefetch ring of x rows (clamped)
        float4 rL[4], rH[4];
#pragma unroll
        for (int d = 0; d < 4; ++d) {
            int rowL = max(baseL + dir * min(d, clL), 0);
            int rowH = max(baseH + dir * min(d, clH), 0);
            rL[d] = *(const float4*)(pL + (size_t)rowL * L);
            rH[d] = *(const float4*)(pH + (size_t)rowH * L);
        }

        for (int k0 = 0; k0 < kMaxPad; k0 += 4) {
#pragma unroll
            for (int kk = 0; kk < 4; ++kk) {
                int k = k0 + kk;

                float4 xL = rL[kk], xH = rH[kk];

                float eL0 = ex2f(xL.x * LOG2E), eL1 = ex2f(xL.y * LOG2E);
                float eL2 = ex2f(xL.z * LOG2E), eL3 = ex2f(xL.w * LOG2E);
                float eH0 = ex2f(xH.x * LOG2E), eH1 = ex2f(xH.y * LOG2E);
                float eH2 = ex2f(xH.z * LOG2E), eH3 = ex2f(xH.w * LOG2E);

                float d0, d1, d2, d3, f0, f1, f2, f3;
                mma16816(d0, d1, d2, d3, A0, A1, A2, A3, b00, b01);
                mma16816(f0, f1, f2, f3, A0, A1, A2, A3, b10, b11);

                // refill ring slot with row k+4
                {
                    int rowL = max(baseL + dir * min(k + 4, clL), 0);
                    int rowH = max(baseH + dir * min(k + 4, clH), 0);
                    rL[kk] = *(const float4*)(pL + (size_t)rowL * L);
                    rH[kk] = *(const float4*)(pH + (size_t)rowH * L);
                }

                u32 n0 = pkbf(d1 * eL1, d0 * eL0);
                u32 n1 = pkbf(d3 * eH1, d2 * eH0);
                u32 n2 = pkbf(f1 * eL3, f0 * eL2);
                u32 n3 = pkbf(f3 * eH3, f2 * eH2);

                bool aL = k < cntL, aH = k < cntH;
                A0 = aL ? n0 : A0;  A2 = aL ? n2 : A2;
                A1 = aH ? n1 : A1;  A3 = aH ? n3 : A3;

                if ((k & 7) == 7) {   // exponent-only rescale per batch row
                    u32 s0 = __shfl_sync(FULL, A0, lane & ~3);
                    u32 s1 = __shfl_sync(FULL, A1, lane & ~3);
                    int eeL = (int)((s0 >> 7) & 0xff) - 127;
                    int eeH = (int)((s1 >> 7) & 0xff) - 127;
                    u32 hL = (u32)(127 - eeL) << 7;
                    u32 hH = (u32)(127 - eeH) << 7;
                    u32 scL = aL ? (hL | (hL << 16)) : 0x3f803f80u;
                    u32 scH = aH ? (hH | (hH << 16)) : 0x3f803f80u;
                    MsL += aL ? eeL : 0;
                    MsH += aH ? eeH : 0;
                    A0 = mulbf2(A0, scL); A2 = mulbf2(A2, scL);
                    A1 = mulbf2(A1, scH); A3 = mulbf2(A3, scH);
                }
            }
        }

        if (!isBwd) {
            sFA[grp][lane][0] = A0; sFA[grp][lane][1] = A1;
            sFA[grp][lane][2] = A2; sFA[grp][lane][3] = A3;
            if (tig == 0) { sMf[grp][g] = MsL; sMf[grp][g + 8] = MsH; }
            __syncthreads();
        } else {
            // beta_m = E * q~ : one more (plain) double-MMA
            float d0, d1, d2, d3, f0, f1, f2, f3;
            mma16816(d0, d1, d2, d3, A0, A1, A2, A3, b00, b01);
            mma16816(f0, f1, f2, f3, A0, A1, A2, A3, b10, b11);
            if (lenL == 1) { d0 = d1 = 1.f; f0 = f1 = 1.f; }
            if (lenH == 1) { d2 = d3 = 1.f; f2 = f3 = 1.f; }

            __syncthreads();

            u32 a0 = sFA[grp][lane][0], a1 = sFA[grp][lane][1];
            u32 a2 = sFA[grp][lane][2], a3 = sFA[grp][lane][3];
            float pLo = d0 * bflo(a0) + d1 * bfhi(a0) + f0 * bflo(a2) + f1 * bfhi(a2);
            float pHi = d2 * bflo(a1) + d3 * bfhi(a1) + f2 * bflo(a3) + f3 * bfhi(a3);
            pLo += __shfl_xor_sync(FULL, pLo, 1);
            pLo += __shfl_xor_sync(FULL, pLo, 2);
            pHi += __shfl_xor_sync(FULL, pHi, 1);
            pHi += __shfl_xor_sync(FULL, pHi, 2);
            float zL = __logf(pLo) + (float)(MsL + sMf[grp][g]) * LN2;
            float zH = __logf(pHi) + (float)(MsH + sMf[grp][g + 8]) * LN2;
            if (tig == 0) {
                out[b_lo] = zL - sScore[grp * 16 + g];
                out[b_hi] = zH - sScore[grp * 16 + g + 8];
            }
        }
    } else {
        // ---------------- emit / transition warps ----------------
        int we = w - 4;
#pragma unroll 1
        for (int k2 = 0; k2 < 8; ++k2) {
            int sl = we * 8 + k2;
            int bb = blockBase + sl;
            const int*   lb = label + (size_t)bb * T;
            const float* xb = x + (size_t)bb * T * L;
            int ll = length[bb];

            float acc = 0.f;
            for (int t = lane; t < ll; t += 32) {
                int lab = lb[t];
                acc += __ldg(xb + t * L + lab);
                if (t >= 1) acc += sT[lb[t - 1] * L + lab];
            }
            acc += __shfl_xor_sync(FULL, acc, 16);
            acc += __shfl_xor_sync(FULL, acc, 8);
            acc += __shfl_xor_sync(FULL, acc, 4);
            acc += __shfl_xor_sync(FULL, acc, 2);
            acc += __shfl_xor_sync(FULL, acc, 1);
            if (lane == 0) sScore[sl] = acc;
        }
        __syncthreads();
    }
}

extern "C" void kernel_launch(void* const* d_in, const int* in_sizes, int n_in,
                              void* d_out, int out_size) {
    const float* x      = (const float*)d_in[0];
    const float* trans  = (const float*)d_in[1];
    const int*   label  = (const int*)d_in[2];
    const int*   length = (const int*)d_in[3];
    float*       out    = (float*)d_out;

    int B = in_sizes[3];                 // 4096
    int T = in_sizes[2] / B;             // 512

    int grid = (B + 31) / 32;            // 32 batches per block, 128 blocks
    crf_kernel<<<grid, 256>>>(x, trans, label, length, out, B, T);
}

// round 12
// speedup vs baseline: 1.3762x; 1.0083x over previous
#include <cuda_runtime.h>

#define FULL 0xffffffffu
typedef unsigned int u32;

constexpr int L = 16;
constexpr float LOG2E = 1.4426950408889634f;
constexpr float LN2   = 0.6931471805599453f;

__device__ __forceinline__ float ex2f(float v) {
    float r; asm("ex2.approx.f32 %0,%1;" : "=f"(r) : "f"(v)); return r;
}
__device__ __forceinline__ u32 pkbf(float hi, float lo) {
    u32 r; asm("cvt.rn.bf16x2.f32 %0,%1,%2;" : "=r"(r) : "f"(hi), "f"(lo)); return r;
}
__device__ __forceinline__ u32 mulbf2(u32 a, u32 b) {
    u32 r; asm("mul.rn.bf16x2 %0,%1,%2;" : "=r"(r) : "r"(a), "r"(b)); return r;
}
__device__ __forceinline__ float bflo(u32 v) { return __uint_as_float(v << 16); }
__device__ __forceinline__ float bfhi(u32 v) { return __uint_as_float(v & 0xffff0000u); }

__device__ __forceinline__ void mma16816(
    float& d0, float& d1, float& d2, float& d3,
    u32 a0, u32 a1, u32 a2, u32 a3, u32 b0, u32 b1)
{
    asm volatile(
        "mma.sync.aligned.m16n8k16.row.col.f32.bf16.bf16.f32 "
        "{%0,%1,%2,%3}, {%4,%5,%6,%7}, {%8,%9}, {%10,%11,%12,%13};"
        : "=f"(d0), "=f"(d1), "=f"(d2), "=f"(d3)
        : "r"(a0), "r"(a1), "r"(a2), "r"(a3), "r"(b0), "r"(b1),
          "f"(0.f), "f"(0.f), "f"(0.f), "f"(0.f));
}

// state permutation on the MMA k/n axes
__host__ __device__ __forceinline__ int sigma(int i) {
    return (i < 8) ? ((i & 1) ? 2 * i - 1 : 2 * i)
                   : ((i & 1) ? 2 * i - 15 : 2 * i - 14);
}

// Grid = 128 blocks x 32 batches. Block = 256 threads = 8 warps:
//  w0-1: fwd recursion (batch groups 0-1, 16 batches each)
//  w2-3: bwd recursion (groups 0-1)
//  w4-7: emit + transition scores (8 batches each)
// One recursion warp per SMSP across the full chip.
// Step body ordered: MMA first (A ready), ex2 block overlaps MMA latency.
__global__ __launch_bounds__(256, 1) void crf_kernel(
    const float* __restrict__ x, const float* __restrict__ trans,
    const int* __restrict__ label, const int* __restrict__ length,
    float* __restrict__ out, int B, int T)
{
    __shared__ float sE[L * L];
    __shared__ float sT[L * L];
    __shared__ u32   sFA[2][32][4];
    __shared__ int   sMf[2][16];
    __shared__ float sScore[32];

    int tid  = threadIdx.x;
    int lane = tid & 31;
    int w    = tid >> 5;
    int g    = lane >> 2;
    int tig  = lane & 3;

    if (tid < L * L) {
        float tv = trans[tid];
        sT[tid] = tv;
        sE[tid] = tv * LOG2E;
    }
    __syncthreads();

    int blockBase = blockIdx.x * 32;

    if (w < 4) {
        bool isBwd = w >= 2;
        int grp = w & 1;
        int bBase = blockBase + grp * 16;
        int b_lo = bBase + g, b_hi = bBase + g + 8;
        int lenL = length[b_lo], lenH = length[b_hi];
        int mL = (lenL - 1) >> 1, mH = (lenH - 1) >> 1;
        int cntL = isBwd ? max(lenL - 2 - mL, 0) : mL;
        int cntH = isBwd ? max(lenH - 2 - mH, 0) : mH;
        int baseL = isBwd ? (lenL - 2) : 1;
        int baseH = isBwd ? (lenH - 2) : 1;
        int dir   = isBwd ? -1 : 1;
        int clL = max(cntL - 1, 0), clH = max(cntH - 1, 0);

        int kMax = max(cntL, cntH);
#pragma unroll
        for (int o = 1; o <= 16; o <<= 1)
            kMax = max(kMax, __shfl_xor_sync(FULL, kMax, o));
        int kMaxPad = (kMax + 3) & ~3;

        // B fragments with sigma on both axes:
        // fwd: B[kap][n] = expE[sigma(kap)][sigma(n)];  bwd: transpose roles.
        u32 b00, b01, b10, b11;
        {
            int r0 = 4 * tig;
            int cA = sigma(g);
            int cB = sigma(g + 8);
            float e00, e01, e02, e03, e10, e11, e12, e13;
            if (!isBwd) {
                e00 = sE[r0 * L + cA];       e01 = sE[(r0 + 1) * L + cA];
                e02 = sE[(r0 + 2) * L + cA]; e03 = sE[(r0 + 3) * L + cA];
                e10 = sE[r0 * L + cB];       e11 = sE[(r0 + 1) * L + cB];
                e12 = sE[(r0 + 2) * L + cB]; e13 = sE[(r0 + 3) * L + cB];
            } else {
                e00 = sE[cA * L + r0];       e01 = sE[cA * L + r0 + 1];
                e02 = sE[cA * L + r0 + 2];   e03 = sE[cA * L + r0 + 3];
                e10 = sE[cB * L + r0];       e11 = sE[cB * L + r0 + 1];
                e12 = sE[cB * L + r0 + 2];   e13 = sE[cB * L + r0 + 3];
            }
            b00 = pkbf(ex2f(e01), ex2f(e00));
            b01 = pkbf(ex2f(e03), ex2f(e02));
            b10 = pkbf(ex2f(e11), ex2f(e10));
            b11 = pkbf(ex2f(e13), ex2f(e12));
        }

        // thread tig owns states 4*tig..4*tig+3 (one float4 per row)
        const float* pL = x + (size_t)b_lo * T * L + tig * 4;
        const float* pH = x + (size_t)b_hi * T * L + tig * 4;

        // init: s = exp(x at row 0 (fwd) / len-1 (bwd))
        int irL = isBwd ? (lenL - 1) : 0;
        int irH = isBwd ? (lenH - 1) : 0;
        float4 iL = *(const float4*)(pL + (size_t)irL * L);
        float4 iH = *(const float4*)(pH + (size_t)irH * L);
        u32 A0 = pkbf(ex2f(iL.y * LOG2E), ex2f(iL.x * LOG2E));
        u32 A1 = pkbf(ex2f(iH.y * LOG2E), ex2f(iH.x * LOG2E));
        u32 A2 = pkbf(ex2f(iL.w * LOG2E), ex2f(iL.z * LOG2E));
        u32 A3 = pkbf(ex2f(iH.w * LOG2E), ex2f(iH.z * LOG2E));
        int MsL = 0, MsH = 0;

        // 4-deep prefetch ring of x rows (clamped)
        float4 rL[4], rH[4];
#pragma unroll
        for (int d = 0; d < 4; ++d) {
            int rowL = max(baseL + dir * min(d, clL), 0);
            int rowH = max(baseH + dir * min(d, clH), 0);
            rL[d] = *(const float4*)(pL + (size_t)rowL * L);
            rH[d] = *(const float4*)(pH + (size_t)rowH * L);
        }

        for (int k0 = 0; k0 < kMaxPad; k0 += 4) {
#pragma unroll
            for (int kk = 0; kk < 4; ++kk) {
                int k = k0 + kk;

                // 1) MMAs FIRST — A is ready from the previous step
                float d0, d1, d2, d3, f0, f1, f2, f3;
                mma16816(d0, d1, d2, d3, A0, A1, A2, A3, b00, b01);
                mma16816(f0, f1, f2, f3, A0, A1, A2, A3, b10, b11);

                // 2) exp block overlaps MMA latency; ordered by consumption
                float4 xL = rL[kk], xH = rH[kk];
                float eL0 = ex2f(xL.x * LOG2E), eL1 = ex2f(xL.y * LOG2E);
                float eH0 = ex2f(xH.x * LOG2E), eH1 = ex2f(xH.y * LOG2E);
                float eL2 = ex2f(xL.z * LOG2E), eL3 = ex2f(xL.w * LOG2E);
                float eH2 = ex2f(xH.z * LOG2E), eH3 = ex2f(xH.w * LOG2E);

                // 3) refill ring slot with row k+4
                {
                    int rowL = max(baseL + dir * min(k + 4, clL), 0);
                    int rowH = max(baseH + dir * min(k + 4, clH), 0);
                    rL[kk] = *(const float4*)(pL + (size_t)rowL * L);
                    rH[kk] = *(const float4*)(pH + (size_t)rowH * L);
                }

                // 4) scale + pack + select
                u32 n0 = pkbf(d1 * eL1, d0 * eL0);
                u32 n1 = pkbf(d3 * eH1, d2 * eH0);
                u32 n2 = pkbf(f1 * eL3, f0 * eL2);
                u32 n3 = pkbf(f3 * eH3, f2 * eH2);

                bool aL = k < cntL, aH = k < cntH;
                A0 = aL ? n0 : A0;  A2 = aL ? n2 : A2;
                A1 = aH ? n1 : A1;  A3 = aH ? n3 : A3;

                if ((k & 7) == 7) {   // exponent-only rescale per batch row
                    u32 s0 = __shfl_sync(FULL, A0, lane & ~3);
                    u32 s1 = __shfl_sync(FULL, A1, lane & ~3);
                    int eeL = (int)((s0 >> 7) & 0xff) - 127;
                    int eeH = (int)((s1 >> 7) & 0xff) - 127;
                    u32 hL = (u32)(127 - eeL) << 7;
                    u32 hH = (u32)(127 - eeH) << 7;
                    u32 scL = aL ? (hL | (hL << 16)) : 0x3f803f80u;
                    u32 scH = aH ? (hH | (hH << 16)) : 0x3f803f80u;
                    MsL += aL ? eeL : 0;
                    MsH += aH ? eeH : 0;
                    A0 = mulbf2(A0, scL); A2 = mulbf2(A2, scL);
                    A1 = mulbf2(A1, scH); A3 = mulbf2(A3, scH);
                }
            }
        }

        if (!isBwd) {
            sFA[grp][lane][0] = A0; sFA[grp][lane][1] = A1;
            sFA[grp][lane][2] = A2; sFA[grp][lane][3] = A3;
            if (tig == 0) { sMf[grp][g] = MsL; sMf[grp][g + 8] = MsH; }
            __syncthreads();
        } else {
            // beta_m = E * q~ : one more (plain) double-MMA
            float d0, d1, d2, d3, f0, f1, f2, f3;
            mma16816(d0, d1, d2, d3, A0, A1, A2, A3, b00, b01);
            mma16816(f0, f1, f2, f3, A0, A1, A2, A3, b10, b11);
            if (lenL == 1) { d0 = d1 = 1.f; f0 = f1 = 1.f; }
            if (lenH == 1) { d2 = d3 = 1.f; f2 = f3 = 1.f; }

            __syncthreads();

            u32 a0 = sFA[grp][lane][0], a1 = sFA[grp][lane][1];
            u32 a2 = sFA[grp][lane][2], a3 = sFA[grp][lane][3];
            float pLo = d0 * bflo(a0) + d1 * bfhi(a0) + f0 * bflo(a2) + f1 * bfhi(a2);
            float pHi = d2 * bflo(a1) + d3 * bfhi(a1) + f2 * bflo(a3) + f3 * bfhi(a3);
            pLo += __shfl_xor_sync(FULL, pLo, 1);
            pLo += __shfl_xor_sync(FULL, pLo, 2);
            pHi += __shfl_xor_sync(FULL, pHi, 1);
            pHi += __shfl_xor_sync(FULL, pHi, 2);
            float zL = __logf(pLo) + (float)(MsL + sMf[grp][g]) * LN2;
            float zH = __logf(pHi) + (float)(MsH + sMf[grp][g + 8]) * LN2;
            if (tig == 0) {
                out[b_lo] = zL - sScore[grp * 16 + g];
                out[b_hi] = zH - sScore[grp * 16 + g + 8];
            }
        }
    } else {
        // ---------------- emit / transition warps ----------------
        int we = w - 4;
#pragma unroll 1
        for (int k2 = 0; k2 < 8; ++k2) {
            int sl = we * 8 + k2;
            int bb = blockBase + sl;
            const int*   lb = label + (size_t)bb * T;
            const float* xb = x + (size_t)bb * T * L;
            int ll = length[bb];

            float acc = 0.f;
            for (int t = lane; t < ll; t += 32) {
                int lab = lb[t];
                acc += __ldg(xb + t * L + lab);
                if (t >= 1) acc += sT[lb[t - 1] * L + lab];
            }
            acc += __shfl_xor_sync(FULL, acc, 16);
            acc += __shfl_xor_sync(FULL, acc, 8);
            acc += __shfl_xor_sync(FULL, acc, 4);
            acc += __shfl_xor_sync(FULL, acc, 2);
            acc += __shfl_xor_sync(FULL, acc, 1);
            if (lane == 0) sScore[sl] = acc;
        }
        __syncthreads();
    }
}

extern "C" void kernel_launch(void* const* d_in, const int* in_sizes, int n_in,
                              void* d_out, int out_size) {
    const float* x      = (const float*)d_in[0];
    const float* trans  = (const float*)d_in[1];
    const int*   label  = (const int*)d_in[2];
    const int*   length = (const int*)d_in[3];
    float*       out    = (float*)d_out;

    int B = in_sizes[3];                 // 4096
    int T = in_sizes[2] / B;             // 512

    int grid = (B + 31) / 32;            // 32 batches per block, 128 blocks
    crf_kernel<<<grid, 256>>>(x, trans, label, length, out, B, T);
}

// round 13
// speedup vs baseline: 1.4735x; 1.0707x over previous
#include <cuda_runtime.h>

#define FULL 0xffffffffu
typedef unsigned int u32;

constexpr int L = 16;
constexpr int RING = 8;
constexpr float LOG2E = 1.4426950408889634f;
constexpr float LN2   = 0.6931471805599453f;

__device__ __forceinline__ float ex2f(float v) {
    float r; asm("ex2.approx.f32 %0,%1;" : "=f"(r) : "f"(v)); return r;
}
__device__ __forceinline__ u32 pkbf(float hi, float lo) {
    u32 r; asm("cvt.rn.bf16x2.f32 %0,%1,%2;" : "=r"(r) : "f"(hi), "f"(lo)); return r;
}
__device__ __forceinline__ u32 mulbf2(u32 a, u32 b) {
    u32 r; asm("mul.rn.bf16x2 %0,%1,%2;" : "=r"(r) : "r"(a), "r"(b)); return r;
}
__device__ __forceinline__ float bflo(u32 v) { return __uint_as_float(v << 16); }
__device__ __forceinline__ float bfhi(u32 v) { return __uint_as_float(v & 0xffff0000u); }

__device__ __forceinline__ void mma16816(
    float& d0, float& d1, float& d2, float& d3,
    u32 a0, u32 a1, u32 a2, u32 a3, u32 b0, u32 b1)
{
    asm volatile(
        "mma.sync.aligned.m16n8k16.row.col.f32.bf16.bf16.f32 "
        "{%0,%1,%2,%3}, {%4,%5,%6,%7}, {%8,%9}, {%10,%11,%12,%13};"
        : "=f"(d0), "=f"(d1), "=f"(d2), "=f"(d3)
        : "r"(a0), "r"(a1), "r"(a2), "r"(a3), "r"(b0), "r"(b1),
          "f"(0.f), "f"(0.f), "f"(0.f), "f"(0.f));
}

// state permutation on the MMA k/n axes
__host__ __device__ __forceinline__ int sigma(int i) {
    return (i < 8) ? ((i & 1) ? 2 * i - 1 : 2 * i)
                   : ((i & 1) ? 2 * i - 15 : 2 * i - 14);
}

// Grid = 128 blocks x 32 batches. Block = 384 threads = 12 warps:
//  w0-3 : fwd recursion, batch groups 0-3 (8 batches each, rows duplicated)
//  w4-7 : bwd recursion, groups 0-3
//  w8-11: emit + transition scores (8 batches each)
// SMSP k hosts fwd-grpk + bwd-grpk (2 independent 8-batch chains, per-SMSP
// issue/MUFU load equal to one 16-batch warp) + one early-finishing emit warp.
// 8 batches live in MMA rows 0-7; rows 8-15 are free duplicates (A=(A0,A0,A2,A2)).
__global__ __launch_bounds__(384, 1) void crf_kernel(
    const float* __restrict__ x, const float* __restrict__ trans,
    const int* __restrict__ label, const int* __restrict__ length,
    float* __restrict__ out, int B, int T)
{
    __shared__ float sE[L * L];
    __shared__ float sT[L * L];
    __shared__ u32   sFA[4][32][2];   // fwd final (A0, A2) per lane
    __shared__ int   sMf[4][8];
    __shared__ float sScore[32];

    int tid  = threadIdx.x;
    int lane = tid & 31;
    int w    = tid >> 5;
    int g    = lane >> 2;     // batch row 0..7
    int tig  = lane & 3;

    if (tid < L * L) {
        float tv = trans[tid];
        sT[tid] = tv;
        sE[tid] = tv * LOG2E;
    }
    __syncthreads();

    int blockBase = blockIdx.x * 32;

    if (w < 8) {
        bool isBwd = w >= 4;
        int grp = w & 3;
        int b = blockBase + grp * 8 + g;
        int len = length[b];
        int m = (len - 1) >> 1;
        int cnt  = isBwd ? max(len - 2 - m, 0) : m;
        int base = isBwd ? (len - 2) : 1;
        int dir  = isBwd ? -1 : 1;
        int cl   = max(cnt - 1, 0);

        int kMax = cnt;
#pragma unroll
        for (int o = 4; o <= 16; o <<= 1)
            kMax = max(kMax, __shfl_xor_sync(FULL, kMax, o));
        int kMaxPad = (kMax + RING - 1) & ~(RING - 1);

        // B fragments with sigma on both axes (same as R11):
        u32 b00, b01, b10, b11;
        {
            int r0 = 4 * tig;
            int cA = sigma(g);
            int cB = sigma(g + 8);
            float e00, e01, e02, e03, e10, e11, e12, e13;
            if (!isBwd) {
                e00 = sE[r0 * L + cA];       e01 = sE[(r0 + 1) * L + cA];
                e02 = sE[(r0 + 2) * L + cA]; e03 = sE[(r0 + 3) * L + cA];
                e10 = sE[r0 * L + cB];       e11 = sE[(r0 + 1) * L + cB];
                e12 = sE[(r0 + 2) * L + cB]; e13 = sE[(r0 + 3) * L + cB];
            } else {
                e00 = sE[cA * L + r0];       e01 = sE[cA * L + r0 + 1];
                e02 = sE[cA * L + r0 + 2];   e03 = sE[cA * L + r0 + 3];
                e10 = sE[cB * L + r0];       e11 = sE[cB * L + r0 + 1];
                e12 = sE[cB * L + r0 + 2];   e13 = sE[cB * L + r0 + 3];
            }
            b00 = pkbf(ex2f(e01), ex2f(e00));
            b01 = pkbf(ex2f(e03), ex2f(e02));
            b10 = pkbf(ex2f(e11), ex2f(e10));
            b11 = pkbf(ex2f(e13), ex2f(e12));
        }

        // thread tig owns states 4*tig..4*tig+3 of batch b (one float4 per row)
        const float* p = x + (size_t)b * T * L + tig * 4;

        // init: s = exp(x at row 0 (fwd) / len-1 (bwd))
        int ir = isBwd ? (len - 1) : 0;
        float4 iv = *(const float4*)(p + (size_t)ir * L);
        u32 A0 = pkbf(ex2f(iv.y * LOG2E), ex2f(iv.x * LOG2E));
        u32 A2 = pkbf(ex2f(iv.w * LOG2E), ex2f(iv.z * LOG2E));
        int Ms = 0;

        // RING-deep prefetch ring of x rows (clamped)
        float4 r[RING];
#pragma unroll
        for (int d = 0; d < RING; ++d) {
            int row = max(base + dir * min(d, cl), 0);
            r[d] = *(const float4*)(p + (size_t)row * L);
        }

        for (int k0 = 0; k0 < kMaxPad; k0 += RING) {
#pragma unroll
            for (int kk = 0; kk < RING; ++kk) {
                int k = k0 + kk;

                float d0, d1, d2, d3, f0, f1, f2, f3;
                mma16816(d0, d1, d2, d3, A0, A0, A2, A2, b00, b01);
                mma16816(f0, f1, f2, f3, A0, A0, A2, A2, b10, b11);

                float4 xv = r[kk];
                float e0 = ex2f(xv.x * LOG2E), e1 = ex2f(xv.y * LOG2E);
                float e2 = ex2f(xv.z * LOG2E), e3 = ex2f(xv.w * LOG2E);

                // refill ring slot with row k+RING
                {
                    int row = max(base + dir * min(k + RING, cl), 0);
                    r[kk] = *(const float4*)(p + (size_t)row * L);
                }

                u32 n0 = pkbf(d1 * e1, d0 * e0);
                u32 n2 = pkbf(f1 * e3, f0 * e2);

                bool act = k < cnt;
                A0 = act ? n0 : A0;
                A2 = act ? n2 : A2;

                if (kk == RING - 1) {   // exponent-only rescale (every 8 steps)
                    u32 s0 = __shfl_sync(FULL, A0, lane & ~3);
                    int ee = (int)((s0 >> 7) & 0xff) - 127;
                    u32 h = (u32)(127 - ee) << 7;
                    u32 sc = act ? (h | (h << 16)) : 0x3f803f80u;
                    Ms += act ? ee : 0;
                    A0 = mulbf2(A0, sc);
                    A2 = mulbf2(A2, sc);
                }
            }
        }

        if (!isBwd) {
            sFA[grp][lane][0] = A0;
            sFA[grp][lane][1] = A2;
            if (tig == 0) sMf[grp][g] = Ms;
            __syncthreads();
        } else {
            // beta_m = E * q~ : one more (plain) double-MMA
            float d0, d1, d2, d3, f0, f1, f2, f3;
            mma16816(d0, d1, d2, d3, A0, A0, A2, A2, b00, b01);
            mma16816(f0, f1, f2, f3, A0, A0, A2, A2, b10, b11);
            if (len == 1) { d0 = d1 = 1.f; f0 = f1 = 1.f; }

            __syncthreads();

            u32 a0 = sFA[grp][lane][0], a2 = sFA[grp][lane][1];
            float pr = d0 * bflo(a0) + d1 * bfhi(a0)
                     + f0 * bflo(a2) + f1 * bfhi(a2);
            pr += __shfl_xor_sync(FULL, pr, 1);
            pr += __shfl_xor_sync(FULL, pr, 2);
            float z = __logf(pr) + (float)(Ms + sMf[grp][g]) * LN2;
            if (tig == 0) out[b] = z - sScore[grp * 8 + g];
        }
    } else {
        // ---------------- emit / transition warps ----------------
        int we = w - 8;
#pragma unroll 1
        for (int k2 = 0; k2 < 8; ++k2) {
            int sl = we * 8 + k2;
            int bb = blockBase + sl;
            const int*   lb = label + (size_t)bb * T;
            const float* xb = x + (size_t)bb * T * L;
            int ll = length[bb];

            float acc = 0.f;
            for (int t = lane; t < ll; t += 32) {
                int lab = lb[t];
                acc += __ldg(xb + t * L + lab);
                if (t >= 1) acc += sT[lb[t - 1] * L + lab];
            }
            acc += __shfl_xor_sync(FULL, acc, 16);
            acc += __shfl_xor_sync(FULL, acc, 8);
            acc += __shfl_xor_sync(FULL, acc, 4);
            acc += __shfl_xor_sync(FULL, acc, 2);
            acc += __shfl_xor_sync(FULL, acc, 1);
            if (lane == 0) sScore[sl] = acc;
        }
        __syncthreads();
    }
}

extern "C" void kernel_launch(void* const* d_in, const int* in_sizes, int n_in,
                              void* d_out, int out_size) {
    const float* x      = (const float*)d_in[0];
    const float* trans  = (const float*)d_in[1];
    const int*   label  = (const int*)d_in[2];
    const int*   length = (const int*)d_in[3];
    float*       out    = (float*)d_out;

    int B = in_sizes[3];                 // 4096
    int T = in_sizes[2] / B;             // 512

    int grid = (B + 31) / 32;            // 32 batches per block, 128 blocks
    crf_kernel<<<grid, 384>>>(x, trans, label, length, out, B, T);
}